// round 5
// baseline (speedup 1.0000x reference)
#include <cuda_runtime.h>
#include <cstdint>

#define LGRID  512
#define BATCH  32768
#define SEG    32                 // states per segment; 31 integration steps each
#define NSEG   16                 // 16 segments cover states 1..511
#define NSTEP1 (LGRID - SEG)      // pass 1 integrates to state 480

// ---------------- pass 1: serial integration, checkpoint stores only ----------------
#define TPB1 64
__global__ __launch_bounds__(TPB1)
void pass1_kernel(const float* __restrict__ s_grid,
                  const float* __restrict__ y0,
                  const float* __restrict__ w,
                  float* __restrict__ out) {
    __shared__ float sh_h[NSTEP1];
    const int tid = threadIdx.x;
    for (int j = tid; j < NSTEP1; j += TPB1)
        sh_h[j] = s_grid[j + 1] - s_grid[j];
    __syncthreads();

    const float w0_  = __ldg(w + 0),  w1_  = __ldg(w + 1),  w2_  = __ldg(w + 2);
    const float w3_  = __ldg(w + 3),  w4_  = __ldg(w + 4),  w5_  = __ldg(w + 5);
    const float w6_  = __ldg(w + 6),  w7_  = __ldg(w + 7),  w8_  = __ldg(w + 8);
    const float w9_  = __ldg(w + 9),  w10_ = __ldg(w + 10), w11_ = __ldg(w + 11);
    const float w12_ = __ldg(w + 12), w13_ = __ldg(w + 13), w14_ = __ldg(w + 14);
    const float w15_ = __ldg(w + 15), w16_ = __ldg(w + 16), w17_ = __ldg(w + 17);
    const float w18_ = __ldg(w + 18), w19_ = __ldg(w + 19), w20_ = __ldg(w + 20);

    const int b = blockIdx.x * TPB1 + tid;

    float A = y0[0 * BATCH + b];
    float T = y0[1 * BATCH + b];
    float N = y0[2 * BATCH + b];
    float C = y0[3 * BATCH + b];

    // state 0
    out[0 * BATCH + b] = A;
    out[1 * BATCH + b] = T;
    out[2 * BATCH + b] = N;
    out[3 * BATCH + b] = C;

    for (int k = 0; k < NSEG - 1; ++k) {
        #pragma unroll 8
        for (int s = 0; s < SEG; ++s) {
            const float h = sh_h[k * SEG + s];
            const float A2 = A * A, T2 = T * T, N2 = N * N, C2 = C * C;
            const float AT = A * T, TN = T * N, NC = N * C;

            const float dA = fmaf(w2_, A2, fmaf(w1_, A, w0_));
            const float tl = fmaf(w5_, T2, fmaf(w4_, T, w3_));
            const float tr = fmaf(w8_, AT, fmaf(w7_, A2, w6_ * A));
            const float dT = tl + tr;
            const float nl = fmaf(w11_, N2, fmaf(w10_, N, w9_));
            const float nr = fmaf(w14_, TN, fmaf(w13_, T2, w12_ * T));
            const float dN = nl + nr;
            const float cl = fmaf(w17_, C2, fmaf(w16_, C, w15_));
            const float cr = fmaf(w20_, NC, fmaf(w19_, N2, w18_ * N));
            const float dC = cl + cr;

            A = fmaf(h, dA, A);
            T = fmaf(h, dT, T);
            N = fmaf(h, dN, N);
            C = fmaf(h, dC, C);
        }
        // checkpoint: state (k+1)*SEG
        float* o = out + (size_t)(k + 1) * SEG * (4 * BATCH) + b;
        o[0 * BATCH] = A;
        o[1 * BATCH] = T;
        o[2 * BATCH] = N;
        o[3 * BATCH] = C;
    }
}

// ---------------- pass 2: 16x segment-parallel re-integration ----------------
// Component-split warp layout (R4): lane = c*8 + q; thread owns component c of
// trajectories j0..j0+3. Cross term (prev component) via shfl_up 8.
#define TPB2 256
#define NBLK2 ((BATCH * NSEG) / TPB2)   // 2048 blocks, 16384 warps

__global__ __launch_bounds__(TPB2)
void pass2_kernel(const float* __restrict__ s_grid,
                  const float* __restrict__ w,
                  float* __restrict__ out) {
    __shared__ float sh_h[SEG - 1];

    const int tid  = threadIdx.x;
    const int lane = tid & 31;

    const int gw  = blockIdx.x * (TPB2 / 32) + (tid >> 5);  // global warp id
    const int seg = gw >> 10;          // 1024 trajectory-warps per segment
    const int tw  = gw & 1023;         // trajectory-warp within segment
    const int s0  = seg * SEG;         // segment start state

    // all warps in a block share the same segment (8 | 1024)
    for (int j = tid; j < SEG - 1; j += TPB2)
        sh_h[j] = s_grid[s0 + j + 1] - s_grid[s0 + j];
    __syncthreads();

    const int c  = lane >> 3;
    const int q  = lane & 7;
    const int j0 = tw * 32 + q * 4;

    // per-component weights: dY = (wa + wb*y + wc*y^2) + p*(wd + we*p + wf*y)
    float wa, wb, wc_, wd, we, wf;
    if (c == 0) {
        wa = __ldg(w + 0); wb = __ldg(w + 1); wc_ = __ldg(w + 2);
        wd = 0.0f; we = 0.0f; wf = 0.0f;
    } else {
        const int base = 3 + 6 * (c - 1);
        wa  = __ldg(w + base + 0);
        wb  = __ldg(w + base + 1);
        wc_ = __ldg(w + base + 2);
        wd  = __ldg(w + base + 3);
        we  = __ldg(w + base + 4);
        wf  = __ldg(w + base + 5);
    }

    // load checkpoint state written by pass 1
    const float4 yv = *(const float4*)(out + (size_t)s0 * (4 * BATCH)
                                           + (size_t)c * BATCH + j0);
    float ya = yv.x, yb = yv.y, yc = yv.z, yd = yv.w;

    #pragma unroll 2
    for (int s = 0; s < SEG - 1; ++s) {
        const float h = sh_h[s];

        const float pa = __shfl_up_sync(0xffffffffu, ya, 8);
        const float pb = __shfl_up_sync(0xffffffffu, yb, 8);
        const float pc = __shfl_up_sync(0xffffffffu, yc, 8);
        const float pd = __shfl_up_sync(0xffffffffu, yd, 8);

        {
            const float y2 = ya * ya;
            float t1 = fmaf(wb, ya, wa);  t1 = fmaf(wc_, y2, t1);
            float u  = fmaf(we, pa, wd);  u  = fmaf(wf, ya, u);
            ya = fmaf(h, fmaf(pa, u, t1), ya);
        }
        {
            const float y2 = yb * yb;
            float t1 = fmaf(wb, yb, wa);  t1 = fmaf(wc_, y2, t1);
            float u  = fmaf(we, pb, wd);  u  = fmaf(wf, yb, u);
            yb = fmaf(h, fmaf(pb, u, t1), yb);
        }
        {
            const float y2 = yc * yc;
            float t1 = fmaf(wb, yc, wa);  t1 = fmaf(wc_, y2, t1);
            float u  = fmaf(we, pc, wd);  u  = fmaf(wf, yc, u);
            yc = fmaf(h, fmaf(pc, u, t1), yc);
        }
        {
            const float y2 = yd * yd;
            float t1 = fmaf(wb, yd, wa);  t1 = fmaf(wc_, y2, t1);
            float u  = fmaf(we, pd, wd);  u  = fmaf(wf, yd, u);
            yd = fmaf(h, fmaf(pd, u, t1), yd);
        }

        float4 o; o.x = ya; o.y = yb; o.z = yc; o.w = yd;
        __stcs((float4*)(out + (size_t)(s0 + s + 1) * (4 * BATCH)
                             + (size_t)c * BATCH + j0), o);
    }
}

extern "C" void kernel_launch(void* const* d_in, const int* in_sizes, int n_in,
                              void* d_out, int out_size) {
    const float* s_grid = (const float*)d_in[0];
    const float* y0     = (const float*)d_in[1];
    const float* w      = (const float*)d_in[2];
    float* out          = (float*)d_out;

    pass1_kernel<<<BATCH / TPB1, TPB1>>>(s_grid, y0, w, out);
    pass2_kernel<<<NBLK2, TPB2>>>(s_grid, w, out);
}

// round 6
// speedup vs baseline: 1.0464x; 1.0464x over previous
#include <cuda_runtime.h>
#include <cstdint>

#define LGRID  512
#define BATCH  32768
#define SEG    32
#define NSEG   16                  // segments: states k*32+1 .. k*32+31
#define TPB    256
#define P1_CTAS (BATCH / TPB)      // 128 pass1 CTAs (1 trajectory / thread)
#define P2_CTAS (NSEG * (BATCH / 32) / (TPB / 32))   // 16*1024/8 = 2048
#define NCTAS  (P1_CTAS + P2_CTAS) // 2176

__device__ unsigned int g_flag[NSEG];

__global__ void zero_flags_kernel() {
    if (threadIdx.x < NSEG) g_flag[threadIdx.x] = 0;
}

__global__ __launch_bounds__(TPB)
void fused_kernel(const float* __restrict__ s_grid,
                  const float* __restrict__ y0,
                  const float* __restrict__ w,
                  float* __restrict__ out) {
    __shared__ float sh_h[LGRID - SEG];   // pass1 uses 480, pass2 uses 31

    const int tid = threadIdx.x;
    const int cta = blockIdx.x;

    if (cta < P1_CTAS) {
        // ---------------- pass 1: serial chain, checkpoint stores ----------------
        for (int j = tid; j < LGRID - SEG; j += TPB)
            sh_h[j] = s_grid[j + 1] - s_grid[j];
        __syncthreads();

        const float w0_  = __ldg(w + 0),  w1_  = __ldg(w + 1),  w2_  = __ldg(w + 2);
        const float w3_  = __ldg(w + 3),  w4_  = __ldg(w + 4),  w5_  = __ldg(w + 5);
        const float w6_  = __ldg(w + 6),  w7_  = __ldg(w + 7),  w8_  = __ldg(w + 8);
        const float w9_  = __ldg(w + 9),  w10_ = __ldg(w + 10), w11_ = __ldg(w + 11);
        const float w12_ = __ldg(w + 12), w13_ = __ldg(w + 13), w14_ = __ldg(w + 14);
        const float w15_ = __ldg(w + 15), w16_ = __ldg(w + 16), w17_ = __ldg(w + 17);
        const float w18_ = __ldg(w + 18), w19_ = __ldg(w + 19), w20_ = __ldg(w + 20);

        const int b = cta * TPB + tid;

        float A = y0[0 * BATCH + b];
        float T = y0[1 * BATCH + b];
        float N = y0[2 * BATCH + b];
        float C = y0[3 * BATCH + b];

        // checkpoint 0 = state 0
        out[0 * BATCH + b] = A;
        out[1 * BATCH + b] = T;
        out[2 * BATCH + b] = N;
        out[3 * BATCH + b] = C;
        __threadfence();
        __syncthreads();
        if (tid == 0) atomicAdd(&g_flag[0], 1u);

        for (int k = 0; k < NSEG - 1; ++k) {
            #pragma unroll
            for (int s = 0; s < SEG; ++s) {
                const float h = sh_h[k * SEG + s];
                const float A2 = A * A, T2 = T * T, N2 = N * N, C2 = C * C;
                const float AT = A * T, TN = T * N, NC = N * C;

                const float dA = fmaf(w2_, A2, fmaf(w1_, A, w0_));
                const float dT = fmaf(w5_, T2, fmaf(w4_, T, w3_))
                               + fmaf(w8_, AT, fmaf(w7_, A2, w6_ * A));
                const float dN = fmaf(w11_, N2, fmaf(w10_, N, w9_))
                               + fmaf(w14_, TN, fmaf(w13_, T2, w12_ * T));
                const float dC = fmaf(w17_, C2, fmaf(w16_, C, w15_))
                               + fmaf(w20_, NC, fmaf(w19_, N2, w18_ * N));

                A = fmaf(h, dA, A);
                T = fmaf(h, dT, T);
                N = fmaf(h, dN, N);
                C = fmaf(h, dC, C);
            }
            // checkpoint k+1 at state (k+1)*SEG  (default caching: pass2 reads it)
            float* o = out + (size_t)(k + 1) * SEG * (4 * BATCH) + b;
            o[0 * BATCH] = A;
            o[1 * BATCH] = T;
            o[2 * BATCH] = N;
            o[3 * BATCH] = C;
            __threadfence();
            __syncthreads();
            if (tid == 0) atomicAdd(&g_flag[k + 1], 1u);
        }
    } else {
        // ---------------- pass 2: segment-parallel re-integration ----------------
        const int u    = cta - P1_CTAS;          // 0..2047
        const int lane = tid & 31;
        const int wid  = tid >> 5;

        const int gw  = u * (TPB / 32) + wid;    // global trajectory-warp id
        const int seg = gw >> 10;                // same for all warps in CTA
        const int tw  = gw & 1023;
        const int s0  = seg * SEG;

        for (int j = tid; j < SEG - 1; j += TPB)
            sh_h[j] = s_grid[s0 + j + 1] - s_grid[s0 + j];

        // component-split layout
        const int c  = lane >> 3;
        const int q  = lane & 7;
        const int j0 = tw * 32 + q * 4;

        float wa, wb, wc_, wd, we, wf;
        if (c == 0) {
            wa = __ldg(w + 0); wb = __ldg(w + 1); wc_ = __ldg(w + 2);
            wd = 0.0f; we = 0.0f; wf = 0.0f;
        } else {
            const int base = 3 + 6 * (c - 1);
            wa  = __ldg(w + base + 0);
            wb  = __ldg(w + base + 1);
            wc_ = __ldg(w + base + 2);
            wd  = __ldg(w + base + 3);
            we  = __ldg(w + base + 4);
            wf  = __ldg(w + base + 5);
        }

        // wait for checkpoint seg
        if (tid == 0) {
            volatile unsigned int* f = (volatile unsigned int*)&g_flag[seg];
            while (*f < (unsigned int)P1_CTAS) __nanosleep(200);
            __threadfence();
        }
        __syncthreads();

        const float4 yv = *(const float4*)(out + (size_t)s0 * (4 * BATCH)
                                               + (size_t)c * BATCH + j0);
        float ya = yv.x, yb = yv.y, yc = yv.z, yd = yv.w;

        #pragma unroll 2
        for (int s = 0; s < SEG - 1; ++s) {
            const float h = sh_h[s];

            const float pa = __shfl_up_sync(0xffffffffu, ya, 8);
            const float pb = __shfl_up_sync(0xffffffffu, yb, 8);
            const float pc = __shfl_up_sync(0xffffffffu, yc, 8);
            const float pd = __shfl_up_sync(0xffffffffu, yd, 8);

            {
                const float y2 = ya * ya;
                float t1 = fmaf(wb, ya, wa);  t1 = fmaf(wc_, y2, t1);
                float uu = fmaf(we, pa, wd);  uu = fmaf(wf, ya, uu);
                ya = fmaf(h, fmaf(pa, uu, t1), ya);
            }
            {
                const float y2 = yb * yb;
                float t1 = fmaf(wb, yb, wa);  t1 = fmaf(wc_, y2, t1);
                float uu = fmaf(we, pb, wd);  uu = fmaf(wf, yb, uu);
                yb = fmaf(h, fmaf(pb, uu, t1), yb);
            }
            {
                const float y2 = yc * yc;
                float t1 = fmaf(wb, yc, wa);  t1 = fmaf(wc_, y2, t1);
                float uu = fmaf(we, pc, wd);  uu = fmaf(wf, yc, uu);
                yc = fmaf(h, fmaf(pc, uu, t1), yc);
            }
            {
                const float y2 = yd * yd;
                float t1 = fmaf(wb, yd, wa);  t1 = fmaf(wc_, y2, t1);
                float uu = fmaf(we, pd, wd);  uu = fmaf(wf, yd, uu);
                yd = fmaf(h, fmaf(pd, uu, t1), yd);
            }

            float4 o; o.x = ya; o.y = yb; o.z = yc; o.w = yd;
            __stcs((float4*)(out + (size_t)(s0 + s + 1) * (4 * BATCH)
                                 + (size_t)c * BATCH + j0), o);
        }
    }
}

extern "C" void kernel_launch(void* const* d_in, const int* in_sizes, int n_in,
                              void* d_out, int out_size) {
    const float* s_grid = (const float*)d_in[0];
    const float* y0     = (const float*)d_in[1];
    const float* w      = (const float*)d_in[2];
    float* out          = (float*)d_out;

    zero_flags_kernel<<<1, 32>>>();
    fused_kernel<<<NCTAS, TPB>>>(s_grid, y0, w, out);
}